// round 15
// baseline (speedup 1.0000x reference)
#include <cuda_runtime.h>
#include <cstdint>

// Problem shape (fixed): x:(32,512,64,64) f32, weight:(1,1,3,3), k=256
#define BB 32
#define NN 512
#define HH 64
#define WW 64
#define IMG_ELEMS (HH * WW)          // 4096
#define IMG_BYTES (IMG_ELEMS * 4)    // 16384

// Scratch (no cudaMalloc allowed)
__device__ float2 g_scores[BB * NN];
__device__ int    g_order[BB * NN];
__device__ int    g_cnt[BB];          // score blocks completed per batch
__device__ int    g_done[BB];         // topk completed per batch
__device__ int    g_fin[BB];          // gather blocks passed per batch

// ---------------------------------------------------------------------------
// Phase 1: warp-per-image conv score (R4/R6 core, MLP=8) + PDL trigger and
// per-batch completion counter epilogue (proven in R13/R14: ~46us, regs 32).
// grid = B*N/8, block = 256 (8 warps = 8 images; batch = blockIdx>>6).
// ---------------------------------------------------------------------------
__global__ __launch_bounds__(256) void score_kernel(
    const float* __restrict__ x, const float* __restrict__ w,
    float2* __restrict__ scores)
{
    asm volatile("griddepcontrol.launch_dependents;" ::: "memory");

    const int li   = threadIdx.x & 31;
    const int img  = blockIdx.x * 8 + (threadIdx.x >> 5);
    const bool tail = (li == 31);                 // cols 62,63: invalid outputs

    const float wc = w[0];   // corners
    const float wE = w[1];   // edges
    const float wm = w[4];   // center

    const float2* b2 = reinterpret_cast<const float2*>(
        x + (size_t)img * IMG_ELEMS) + li;        // 32 float2 per row

    float Ha1[2], Hm1[2], Ha2[2], Hm2[2];
    float s = 0.f, e = 0.f;

    float2 v[8];

#pragma unroll
    for (int i = 0; i < 8; i++) v[i] = b2[i * 32];

    {
        float nx = __shfl_down_sync(0xffffffffu, v[0].x, 1);
        float ny = __shfl_down_sync(0xffffffffu, v[0].y, 1);
        Ha2[0] = v[0].x + nx;  Hm2[0] = v[0].y;
        Ha2[1] = v[0].y + ny;  Hm2[1] = nx;
        nx = __shfl_down_sync(0xffffffffu, v[1].x, 1);
        ny = __shfl_down_sync(0xffffffffu, v[1].y, 1);
        Ha1[0] = v[1].x + nx;  Hm1[0] = v[1].y;
        Ha1[1] = v[1].y + ny;  Hm1[1] = nx;
    }

#define DO_ROW(vv)                                                          \
    {                                                                       \
        float nx = __shfl_down_sync(0xffffffffu, (vv).x, 1);                \
        float ny = __shfl_down_sync(0xffffffffu, (vv).y, 1);                \
        float Hac0 = (vv).x + nx, Hmc0 = (vv).y;                            \
        float Hac1 = (vv).y + ny, Hmc1 = nx;                                \
        float s1a = Ha2[0] + Hac0;                                          \
        float s2a = (Hm2[0] + Hmc0) + Ha1[0];                               \
        float vra = fmaf(wc, s1a, fmaf(wE, s2a, wm * Hm1[0]));              \
        float s1b = Ha2[1] + Hac1;                                          \
        float s2b = (Hm2[1] + Hmc1) + Ha1[1];                               \
        float vrb = fmaf(wc, s1b, fmaf(wE, s2b, wm * Hm1[1]));              \
        float row = fabsf(vra) + fabsf(vrb);                                \
        if (tail) row = 0.f;                                                \
        float tt  = __fadd_rn(s, row);                                      \
        e = __fadd_rn(e, __fadd_rn(__fsub_rn(s, tt), row));                 \
        s = tt;                                                             \
        Ha2[0] = Ha1[0]; Hm2[0] = Hm1[0]; Ha1[0] = Hac0; Hm1[0] = Hmc0;     \
        Ha2[1] = Ha1[1]; Hm2[1] = Hm1[1]; Ha1[1] = Hac1; Hm1[1] = Hmc1;     \
    }

#pragma unroll
    for (int i = 2; i < 8; i++) DO_ROW(v[i]);

    for (int c = 1; c < 8; c++) {
#pragma unroll
        for (int i = 0; i < 8; i++) v[i] = b2[(c * 8 + i) * 32];
#pragma unroll
        for (int i = 0; i < 8; i++) DO_ROW(v[i]);
    }
#undef DO_ROW

#pragma unroll
    for (int off = 16; off; off >>= 1) {
        float s2 = __shfl_down_sync(0xffffffffu, s, off);
        float e2 = __shfl_down_sync(0xffffffffu, e, off);
        float tt  = __fadd_rn(s, s2);
        float z   = __fsub_rn(tt, s);
        float err = __fadd_rn(__fsub_rn(s, __fsub_rn(tt, z)), __fsub_rn(s2, z));
        e = __fadd_rn(__fadd_rn(e, e2), err);
        s = tt;
    }

    if (li == 0) {
        float h = __fadd_rn(s, e);
        float l = __fadd_rn(__fsub_rn(s, h), e);
        scores[img] = make_float2(h, l);
        __threadfence();                 // publish this warp's score gpu-wide
    }
    __syncthreads();
    if (threadIdx.x == 0)
        atomicAdd(&g_cnt[blockIdx.x >> 6], 1);   // 64 blocks per batch
}

// ---------------------------------------------------------------------------
// Phase 2 (PDL, dataflow): 32 blocks, one per batch. Spin on the batch's
// score counter, rank all 512 candidates (u64 sortable keys), publish order
// and the batch-done flag.
// ---------------------------------------------------------------------------
__device__ __forceinline__ uint32_t f2u_sortable(float f) {
    uint32_t u = __float_as_uint(f);
    return u ^ ((u & 0x80000000u) ? 0xFFFFFFFFu : 0x80000000u);
}

__global__ __launch_bounds__(NN) void topk_kernel(
    const float2* __restrict__ scores, int* __restrict__ order, int k)
{
    asm volatile("griddepcontrol.launch_dependents;" ::: "memory");

    __shared__ unsigned long long sk[NN];
    const int b = blockIdx.x;
    const int n = threadIdx.x;

    if (n == 0) {
        while (__ldcg(&g_cnt[b]) < 64) __nanosleep(32);
    }
    __syncthreads();
    __threadfence();                          // acquire side of the handoff

    float2 f = __ldcg(&scores[b * NN + n]);
    unsigned long long key =
        ((unsigned long long)f2u_sortable(f.x) << 32) | f2u_sortable(f.y);
    sk[n] = key;
    __syncthreads();

    int rank = 0;
#pragma unroll 8
    for (int m = 0; m < NN; m++) {
        unsigned long long o = sk[m];
        rank += (o > key) || (o == key && m < n);
    }
    if (rank < k) order[b * k + rank] = n;
    __threadfence();                          // publish my order entry
    __syncthreads();                          // all entries published
    if (n == 0) atomicExch(&g_done[b], 1);    // release the batch
}

// ---------------------------------------------------------------------------
// Phase 3 (PDL, dataflow): R10-proven bulk-copy ring, 32-thread blocks so it
// co-resides with score from t=0. 8 blocks per batch, 32 images each; each
// block spins on its batch's done flag. 8th block self-resets counters.
// ---------------------------------------------------------------------------
#define GS 6          // ring stages
#define GD 4          // prefetch depth (<= GS-2 for WAR safety)

__device__ __forceinline__ void mbar_wait(uint32_t mbar, uint32_t parity) {
    uint32_t done;
    do {
        asm volatile(
            "{\n\t.reg .pred p;\n\t"
            "mbarrier.try_wait.parity.shared.b64 p, [%1], %2;\n\t"
            "selp.b32 %0, 1, 0, p;\n\t}"
            : "=r"(done) : "r"(mbar), "r"(parity) : "memory");
    } while (!done);
}

__device__ __forceinline__ void bulk_load(uint32_t dst_smem, const void* src,
                                          uint32_t mbar) {
    asm volatile(
        "mbarrier.arrive.expect_tx.shared.b64 _, [%0], %1;"
        :: "r"(mbar), "r"((uint32_t)IMG_BYTES) : "memory");
    asm volatile(
        "cp.async.bulk.shared::cluster.global.mbarrier::complete_tx::bytes "
        "[%0], [%1], %2, [%3];"
        :: "r"(dst_smem), "l"(src), "r"((uint32_t)IMG_BYTES), "r"(mbar)
        : "memory");
}

__global__ __launch_bounds__(32) void gather_kernel(
    const float* __restrict__ x, const int* __restrict__ order,
    float* __restrict__ out, int k)
{
    extern __shared__ __align__(128) char dsm[];
    if (threadIdx.x != 0) return;   // 1 control thread; async engines move data

    const uint32_t buf0  = (uint32_t)__cvta_generic_to_shared(dsm);
    const uint32_t mbar0 = buf0 + GS * IMG_BYTES;

    // setup before the data dependency
#pragma unroll
    for (int st = 0; st < GS; st++)
        asm volatile("mbarrier.init.shared.b64 [%0], 1;"
                     :: "r"(mbar0 + st * 8) : "memory");
    asm volatile("fence.proxy.async.shared::cta;" ::: "memory");

    const int batch = blockIdx.x >> 3;
    const int isl   = k >> 3;                  // 32 images per block
    const int r0    = (blockIdx.x & 7) * isl;

    // wait for this batch's topk
    while (__ldcg(&g_done[batch]) == 0) __nanosleep(64);
    __threadfence();

    // self-reset: the 8th block per batch zeroes the counters for next replay
    {
        int old = atomicAdd(&g_fin[batch], 1);
        if (old == 7) {
            g_cnt[batch]  = 0;
            g_done[batch] = 0;
            g_fin[batch]  = 0;
        }
    }

    const size_t xrow  = (size_t)batch * NN;
    const size_t obase = (size_t)batch * k + r0;
    const int*   ord   = order + batch * k + r0;

    // prologue: GD loads in flight
#pragma unroll
    for (int j = 0; j < GD; j++)
        bulk_load(buf0 + (j % GS) * IMG_BYTES,
                  x + (xrow + __ldcg(&ord[j])) * IMG_ELEMS,
                  mbar0 + (j % GS) * 8);

    for (int j = 0; j < isl; j++) {
        const int st = j % GS;
        mbar_wait(mbar0 + st * 8, (j / GS) & 1);

        const float* dst = out + (obase + j) * IMG_ELEMS;
        asm volatile(
            "cp.async.bulk.global.shared::cta.bulk_group [%0], [%1], %2;"
            :: "l"(dst), "r"(buf0 + st * IMG_BYTES), "r"((uint32_t)IMG_BYTES)
            : "memory");
        asm volatile("cp.async.bulk.commit_group;" ::: "memory");

        const int jn = j + GD;
        if (jn < isl) {
            // stage jn%GS last stored at iter jn-GS <= j-2; committed = j+1,
            // pending <= GS-GD => that store's smem read is complete.
            asm volatile("cp.async.bulk.wait_group.read %0;"
                         :: "n"(GS - GD) : "memory");
            bulk_load(buf0 + (jn % GS) * IMG_BYTES,
                      x + (xrow + __ldcg(&ord[jn])) * IMG_ELEMS,
                      mbar0 + (jn % GS) * 8);
        }
    }
    asm volatile("cp.async.bulk.wait_group 0;" ::: "memory");
}

// ---------------------------------------------------------------------------
extern "C" void kernel_launch(void* const* d_in, const int* in_sizes, int n_in,
                              void* d_out, int out_size)
{
    const float* x = (const float*)d_in[0];
    const float* w = (const float*)d_in[1];
    float* out = (float*)d_out;

    const int k = out_size / (BB * IMG_ELEMS);   // = 256

    const int gather_smem = GS * IMG_BYTES + GS * 8;   // 98352 B
    static int attr_set = 0;
    if (!attr_set) {
        cudaFuncSetAttribute(gather_kernel,
                             cudaFuncAttributeMaxDynamicSharedMemorySize,
                             gather_smem);
        attr_set = 1;
    }

    // node 1: score with PDL trigger at entry
    score_kernel<<<(BB * NN) / 8, 256>>>(x, w, g_scores);

    // node 2: topk, PDL on score (launches immediately, spins per batch)
    {
        cudaLaunchAttribute at[1];
        at[0].id = cudaLaunchAttributeProgrammaticStreamSerialization;
        at[0].val.programmaticStreamSerializationAllowed = 1;
        cudaLaunchConfig_t cfg = {};
        cfg.gridDim  = dim3(BB, 1, 1);
        cfg.blockDim = dim3(NN, 1, 1);
        cfg.attrs    = at;
        cfg.numAttrs = 1;
        float2* sc = g_scores;
        int*    od = g_order;
        cudaLaunchKernelEx(&cfg, topk_kernel, (const float2*)sc, od, k);
    }

    // node 3: gather, PDL on topk (launches immediately, spins per batch)
    {
        cudaLaunchAttribute at[1];
        at[0].id = cudaLaunchAttributeProgrammaticStreamSerialization;
        at[0].val.programmaticStreamSerializationAllowed = 1;
        cudaLaunchConfig_t cfg = {};
        cfg.gridDim          = dim3(BB * 8, 1, 1);
        cfg.blockDim         = dim3(32, 1, 1);
        cfg.dynamicSmemBytes = gather_smem;
        cfg.attrs            = at;
        cfg.numAttrs         = 1;
        int* od = g_order;
        cudaLaunchKernelEx(&cfg, gather_kernel, x, (const int*)od, out, k);
    }
}

// round 16
// speedup vs baseline: 1.0634x; 1.0634x over previous
#include <cuda_runtime.h>
#include <cstdint>

// Problem shape (fixed): x:(32,512,64,64) f32, weight:(1,1,3,3), k=256
#define BB 32
#define NN 512
#define HH 64
#define WW 64
#define IMG_ELEMS (HH * WW)          // 4096
#define IMG_BYTES (IMG_ELEMS * 4)    // 16384

// Scratch (no cudaMalloc allowed)
__device__ float2 g_scores[BB * NN];
__device__ int    g_order[BB * NN];

// ---------------------------------------------------------------------------
// Phase 1 (champion R4/R6 codegen — body untouched): warp-per-image conv
// score. Lane li owns cols 2li,2li+1. Rows in chunks of 8: all 8 LDG.64
// issued before compute (MLP=8). Trailing PDL trigger lets the next node's
// launch overlap this grid's drain.
// grid = B*N/8, block = 256 (8 warps = 8 images).
// ---------------------------------------------------------------------------
__global__ __launch_bounds__(256) void score_kernel(
    const float* __restrict__ x, const float* __restrict__ w,
    float2* __restrict__ scores)
{
    const int li   = threadIdx.x & 31;
    const int img  = blockIdx.x * 8 + (threadIdx.x >> 5);
    const bool tail = (li == 31);                 // cols 62,63: invalid outputs

    const float wc = w[0];   // corners
    const float wE = w[1];   // edges
    const float wm = w[4];   // center

    const float2* b2 = reinterpret_cast<const float2*>(
        x + (size_t)img * IMG_ELEMS) + li;        // 32 float2 per row

    float Ha1[2], Hm1[2], Ha2[2], Hm2[2];
    float s = 0.f, e = 0.f;

    float2 v[8];

#pragma unroll
    for (int i = 0; i < 8; i++) v[i] = b2[i * 32];

    {
        float nx = __shfl_down_sync(0xffffffffu, v[0].x, 1);
        float ny = __shfl_down_sync(0xffffffffu, v[0].y, 1);
        Ha2[0] = v[0].x + nx;  Hm2[0] = v[0].y;
        Ha2[1] = v[0].y + ny;  Hm2[1] = nx;
        nx = __shfl_down_sync(0xffffffffu, v[1].x, 1);
        ny = __shfl_down_sync(0xffffffffu, v[1].y, 1);
        Ha1[0] = v[1].x + nx;  Hm1[0] = v[1].y;
        Ha1[1] = v[1].y + ny;  Hm1[1] = nx;
    }

#define DO_ROW(vv)                                                          \
    {                                                                       \
        float nx = __shfl_down_sync(0xffffffffu, (vv).x, 1);                \
        float ny = __shfl_down_sync(0xffffffffu, (vv).y, 1);                \
        float Hac0 = (vv).x + nx, Hmc0 = (vv).y;                            \
        float Hac1 = (vv).y + ny, Hmc1 = nx;                                \
        float s1a = Ha2[0] + Hac0;                                          \
        float s2a = (Hm2[0] + Hmc0) + Ha1[0];                               \
        float vra = fmaf(wc, s1a, fmaf(wE, s2a, wm * Hm1[0]));              \
        float s1b = Ha2[1] + Hac1;                                          \
        float s2b = (Hm2[1] + Hmc1) + Ha1[1];                               \
        float vrb = fmaf(wc, s1b, fmaf(wE, s2b, wm * Hm1[1]));              \
        float row = fabsf(vra) + fabsf(vrb);                                \
        if (tail) row = 0.f;                                                \
        float tt  = __fadd_rn(s, row);                                      \
        e = __fadd_rn(e, __fadd_rn(__fsub_rn(s, tt), row));                 \
        s = tt;                                                             \
        Ha2[0] = Ha1[0]; Hm2[0] = Hm1[0]; Ha1[0] = Hac0; Hm1[0] = Hmc0;     \
        Ha2[1] = Ha1[1]; Hm2[1] = Hm1[1]; Ha1[1] = Hac1; Hm1[1] = Hmc1;     \
    }

#pragma unroll
    for (int i = 2; i < 8; i++) DO_ROW(v[i]);

    for (int c = 1; c < 8; c++) {
#pragma unroll
        for (int i = 0; i < 8; i++) v[i] = b2[(c * 8 + i) * 32];
#pragma unroll
        for (int i = 0; i < 8; i++) DO_ROW(v[i]);
    }
#undef DO_ROW

#pragma unroll
    for (int off = 16; off; off >>= 1) {
        float s2 = __shfl_down_sync(0xffffffffu, s, off);
        float e2 = __shfl_down_sync(0xffffffffu, e, off);
        float tt  = __fadd_rn(s, s2);
        float z   = __fsub_rn(tt, s);
        float err = __fadd_rn(__fsub_rn(s, __fsub_rn(tt, z)), __fsub_rn(s2, z));
        e = __fadd_rn(__fadd_rn(e, e2), err);
        s = tt;
    }

    if (li == 0) {
        float h = __fadd_rn(s, e);
        float l = __fadd_rn(__fsub_rn(s, h), e);
        scores[img] = make_float2(h, l);
    }

    // PDL trigger: this CTA's work (incl. the score store) is done.
    asm volatile("griddepcontrol.launch_dependents;" ::: "memory");
}

// ---------------------------------------------------------------------------
// Phase 2: top-k via sortable u64 keys. PDL secondary: launches during the
// score drain; griddepcontrol.wait releases at score completion (no spin).
// ---------------------------------------------------------------------------
__device__ __forceinline__ uint32_t f2u_sortable(float f) {
    uint32_t u = __float_as_uint(f);
    return u ^ ((u & 0x80000000u) ? 0xFFFFFFFFu : 0x80000000u);
}

__global__ __launch_bounds__(NN) void topk_kernel(
    const float2* __restrict__ scores, int* __restrict__ order, int k)
{
    __shared__ unsigned long long sk[NN];
    const int b = blockIdx.x;
    const int n = threadIdx.x;

    asm volatile("griddepcontrol.wait;" ::: "memory");   // score grid done

    float2 f = scores[b * NN + n];
    unsigned long long key =
        ((unsigned long long)f2u_sortable(f.x) << 32) | f2u_sortable(f.y);
    sk[n] = key;
    __syncthreads();

    int rank = 0;
#pragma unroll 8
    for (int m = 0; m < NN; m++) {
        unsigned long long o = sk[m];
        rank += (o > key) || (o == key && m < n);
    }
    if (rank < k) order[b * k + rank] = n;

    // PDL trigger for the gather node.
    asm volatile("griddepcontrol.launch_dependents;" ::: "memory");
}

// ---------------------------------------------------------------------------
// Phase 3 (champion R10/R11): PERSISTENT gather via async bulk copies
// (UBLKCP in, bulk store out). 296 blocks (2/SM), 6x16KB smem ring, 4 loads
// in flight. PDL secondary: ring/mbarrier setup happens BEFORE the wait.
// ---------------------------------------------------------------------------
#define GS    6       // ring stages
#define GD    4       // prefetch depth (<= GS-2 for WAR safety)
#define GGRID 296     // 2 blocks/SM x 148

__device__ __forceinline__ void mbar_wait(uint32_t mbar, uint32_t parity) {
    uint32_t done;
    do {
        asm volatile(
            "{\n\t.reg .pred p;\n\t"
            "mbarrier.try_wait.parity.shared.b64 p, [%1], %2;\n\t"
            "selp.b32 %0, 1, 0, p;\n\t}"
            : "=r"(done) : "r"(mbar), "r"(parity) : "memory");
    } while (!done);
}

__device__ __forceinline__ void bulk_load(uint32_t dst_smem, const void* src,
                                          uint32_t mbar) {
    asm volatile(
        "mbarrier.arrive.expect_tx.shared.b64 _, [%0], %1;"
        :: "r"(mbar), "r"((uint32_t)IMG_BYTES) : "memory");
    asm volatile(
        "cp.async.bulk.shared::cluster.global.mbarrier::complete_tx::bytes "
        "[%0], [%1], %2, [%3];"
        :: "r"(dst_smem), "l"(src), "r"((uint32_t)IMG_BYTES), "r"(mbar)
        : "memory");
}

__global__ __launch_bounds__(32) void gather_kernel(
    const float* __restrict__ x, const int* __restrict__ order,
    float* __restrict__ out, int k, int total)
{
    extern __shared__ __align__(128) char dsm[];
    if (threadIdx.x != 0) return;   // 1 control thread; async engines move data

    const uint32_t buf0  = (uint32_t)__cvta_generic_to_shared(dsm);
    const uint32_t mbar0 = buf0 + GS * IMG_BYTES;

    // ---- setup independent of topk output: runs before the dependency wait
#pragma unroll
    for (int st = 0; st < GS; st++)
        asm volatile("mbarrier.init.shared.b64 [%0], 1;"
                     :: "r"(mbar0 + st * 8) : "memory");
    asm volatile("fence.proxy.async.shared::cta;" ::: "memory");

    const int g     = blockIdx.x;
    const int start = (int)(((long long)g * total) / GGRID);
    const int end   = (int)(((long long)(g + 1) * total) / GGRID);
    const int n     = end - start;

    asm volatile("griddepcontrol.wait;" ::: "memory");   // topk grid done
    if (n <= 0) return;

    // prologue: up to GD loads in flight
    const int pd = (n < GD) ? n : GD;
    for (int j = 0; j < pd; j++) {
        const int bj = start + j;
        const int nn = __ldg(&order[bj]);
        bulk_load(buf0 + (j % GS) * IMG_BYTES,
                  x + ((size_t)(bj / k) * NN + nn) * IMG_ELEMS,
                  mbar0 + (j % GS) * 8);
    }

    for (int j = 0; j < n; j++) {
        const int st = j % GS;
        mbar_wait(mbar0 + st * 8, (j / GS) & 1);

        const float* dst = out + (size_t)(start + j) * IMG_ELEMS;
        asm volatile(
            "cp.async.bulk.global.shared::cta.bulk_group [%0], [%1], %2;"
            :: "l"(dst), "r"(buf0 + st * IMG_BYTES), "r"((uint32_t)IMG_BYTES)
            : "memory");
        asm volatile("cp.async.bulk.commit_group;" ::: "memory");

        const int jn = j + GD;
        if (jn < n) {
            // stage jn%GS last stored at iter jn-GS <= j-2; committed = j+1,
            // pending <= GS-GD => that store's smem read is complete.
            asm volatile("cp.async.bulk.wait_group.read %0;"
                         :: "n"(GS - GD) : "memory");
            const int bj = start + jn;
            const int nn = __ldg(&order[bj]);
            bulk_load(buf0 + (jn % GS) * IMG_BYTES,
                      x + ((size_t)(bj / k) * NN + nn) * IMG_ELEMS,
                      mbar0 + (jn % GS) * 8);
        }
    }
    asm volatile("cp.async.bulk.wait_group 0;" ::: "memory");
}

// ---------------------------------------------------------------------------
extern "C" void kernel_launch(void* const* d_in, const int* in_sizes, int n_in,
                              void* d_out, int out_size)
{
    const float* x = (const float*)d_in[0];
    const float* w = (const float*)d_in[1];
    float* out = (float*)d_out;

    const int k = out_size / (BB * IMG_ELEMS);   // = 256
    const int total = BB * k;                    // 8192 output images

    const int gather_smem = GS * IMG_BYTES + GS * 8;   // 98352 B
    static int attr_set = 0;
    if (!attr_set) {
        cudaFuncSetAttribute(gather_kernel,
                             cudaFuncAttributeMaxDynamicSharedMemorySize,
                             gather_smem);
        attr_set = 1;
    }

    // node 1: score (plain launch; ends with launch_dependents)
    score_kernel<<<(BB * NN) / 8, 256>>>(x, w, g_scores);

    // node 2: topk with programmatic dependent launch on score
    {
        cudaLaunchAttribute at[1];
        at[0].id = cudaLaunchAttributeProgrammaticStreamSerialization;
        at[0].val.programmaticStreamSerializationAllowed = 1;
        cudaLaunchConfig_t cfg = {};
        cfg.gridDim  = dim3(BB, 1, 1);
        cfg.blockDim = dim3(NN, 1, 1);
        cfg.attrs    = at;
        cfg.numAttrs = 1;
        float2* sc = g_scores;
        int*    od = g_order;
        cudaLaunchKernelEx(&cfg, topk_kernel, (const float2*)sc, od, k);
    }

    // node 3: gather with programmatic dependent launch on topk
    {
        cudaLaunchAttribute at[1];
        at[0].id = cudaLaunchAttributeProgrammaticStreamSerialization;
        at[0].val.programmaticStreamSerializationAllowed = 1;
        cudaLaunchConfig_t cfg = {};
        cfg.gridDim          = dim3(GGRID, 1, 1);
        cfg.blockDim         = dim3(32, 1, 1);
        cfg.dynamicSmemBytes = gather_smem;
        cfg.attrs            = at;
        cfg.numAttrs         = 1;
        int* od = g_order;
        cudaLaunchKernelEx(&cfg, gather_kernel,
                           x, (const int*)od, out, k, total);
    }
}